// round 5
// baseline (speedup 1.0000x reference)
#include <cuda_runtime.h>
#include <cstdint>

#define D 128
#define N_MAX 50064
#define E_MAX 500000
#define FB 160          // fill blocks appended to kernel A

// ---- device scratch (no allocations; .bss zero at load, kernels self-clean) ----
__device__ float g_h[(size_t)N_MAX * D];   // h' = dis[r] * (x @ W)[r]
__device__ int   g_cnt[N_MAX];             // in-degree (excl. self); zeroed by k_final
__device__ float g_dis[N_MAX];             // rsqrt(1 + cnt)
__device__ int   g_start[N_MAX];
__device__ int   g_cursor[N_MAX];
__device__ int   g_adj[E_MAX];
__device__ int   g_total;                  // ticket; zeroed by k_final
__device__ float g_colstats[2 * D];        // zeroed by k_count

// ---------------------------------------------------------------------------
// K1: in-degree count (grid-stride); block 0 zeros column stats
// ---------------------------------------------------------------------------
__global__ void k_count(const int* __restrict__ pos, int E) {
    if (blockIdx.x == 0) g_colstats[threadIdx.x] = 0.0f;   // 256 == 2*D
    for (int e = blockIdx.x * 256 + threadIdx.x; e < E; e += gridDim.x * 256)
        atomicAdd(&g_cnt[pos[(size_t)E + e]], 1);
}

// ---------------------------------------------------------------------------
// K2: segment allocation — block scan + one atomic ticket; dis; cursor
// ---------------------------------------------------------------------------
__global__ void k_alloc(int N) {
    __shared__ int sh[256];
    __shared__ int base;
    int t = threadIdx.x;
    int i = blockIdx.x * 256 + t;
    int c = (i < N) ? g_cnt[i] : 0;
    sh[t] = c;
    __syncthreads();
    for (int off = 1; off < 256; off <<= 1) {
        int v = (t >= off) ? sh[t - off] : 0;
        __syncthreads();
        sh[t] += v;
        __syncthreads();
    }
    if (t == 255) base = atomicAdd(&g_total, sh[255]);
    __syncthreads();
    if (i < N) {
        int start = base + sh[t] - c;
        g_start[i]  = start;
        g_cursor[i] = start;
        g_dis[i]    = rsqrtf(1.0f + (float)c);
    }
}

// ---------------------------------------------------------------------------
// Kernel A (block-specialized):
//   blocks [0, GB)     : h' = dis[r] * (x @ W)  (fp32x2 GEMM, 128x128 tile)
//   blocks [GB, GB+FB) : CSC adjacency fill (independent of h)
// ---------------------------------------------------------------------------
#define FMA2(acc, a, b) asm("fma.rn.f32x2 %0, %1, %2, %0;" : "+l"(acc) : "l"(a), "l"(b))

__global__ void __launch_bounds__(256) kA(const float* __restrict__ x,
                                          const float* __restrict__ W,
                                          const int* __restrict__ pos,
                                          int N, int E, int GB) {
    if (blockIdx.x >= GB) {
        // ---- fill path ----
        int b = blockIdx.x - GB;
        for (int e = b * 256 + threadIdx.x; e < E; e += FB * 256) {
            int col = pos[(size_t)E + e];
            int p = atomicAdd(&g_cursor[col], 1);
            g_adj[p] = pos[e];
        }
        return;
    }

    // ---- GEMM path ----
    __shared__ float xs[16][128];   // transposed x tile
    __shared__ float ws[16][128];   // W tile

    const int t  = threadIdx.x;
    const int r0 = blockIdx.x * 128;
    const int cg = t & 15;
    const int rg = t >> 4;

    unsigned long long acc[8][4];
#pragma unroll
    for (int i = 0; i < 8; i++)
#pragma unroll
        for (int j = 0; j < 4; j++) acc[i][j] = 0ull;

    for (int k0 = 0; k0 < D; k0 += 16) {
        __syncthreads();
#pragma unroll
        for (int u = 0; u < 2; u++) {
            int id  = t + u * 256;
            int row = id >> 2;
            int kq  = (id & 3) * 4;
            float4 v = make_float4(0.f, 0.f, 0.f, 0.f);
            int gr = r0 + row;
            if (gr < N) v = *(const float4*)(x + (size_t)gr * D + k0 + kq);
            xs[kq + 0][row] = v.x;
            xs[kq + 1][row] = v.y;
            xs[kq + 2][row] = v.z;
            xs[kq + 3][row] = v.w;
        }
#pragma unroll
        for (int u = 0; u < 2; u++) {
            int id = t + u * 256;
            int kk = id >> 5;
            int c4 = id & 31;
            *(float4*)&ws[kk][c4 * 4] =
                *(const float4*)(W + (size_t)(k0 + kk) * D + c4 * 4);
        }
        __syncthreads();

#pragma unroll
        for (int kk = 0; kk < 16; kk++) {
            ulonglong2 wA = *(const ulonglong2*)&ws[kk][cg * 8];
            ulonglong2 wB = *(const ulonglong2*)&ws[kk][cg * 8 + 4];
            float4 xa = *(const float4*)&xs[kk][rg * 8];
            float4 xb = *(const float4*)&xs[kk][rg * 8 + 4];
            float xv[8] = {xa.x, xa.y, xa.z, xa.w, xb.x, xb.y, xb.z, xb.w};
#pragma unroll
            for (int i = 0; i < 8; i++) {
                unsigned long long xd;
                asm("mov.b64 %0, {%1, %1};" : "=l"(xd) : "f"(xv[i]));
                FMA2(acc[i][0], xd, wA.x);
                FMA2(acc[i][1], xd, wA.y);
                FMA2(acc[i][2], xd, wB.x);
                FMA2(acc[i][3], xd, wB.y);
            }
        }
    }

#pragma unroll
    for (int i = 0; i < 8; i++) {
        int gr = r0 + rg * 8 + i;
        if (gr < N) {
            float s = g_dis[gr];
            float2 p0 = *(float2*)&acc[i][0];
            float2 p1 = *(float2*)&acc[i][1];
            float2 p2 = *(float2*)&acc[i][2];
            float2 p3 = *(float2*)&acc[i][3];
            *(float4*)(g_h + (size_t)gr * D + cg * 8) =
                make_float4(p0.x * s, p0.y * s, p1.x * s, p1.y * s);
            *(float4*)(g_h + (size_t)gr * D + cg * 8 + 4) =
                make_float4(p2.x * s, p2.y * s, p3.x * s, p3.y * s);
        }
    }
}

// ---------------------------------------------------------------------------
// K3: gather — TWO nodes per warp (8 loads in flight), pure adds,
//     fused column stats.  out[c] = dis[c] * (h'[c] + sum_in h'[r])
// ---------------------------------------------------------------------------
__global__ void __launch_bounds__(256) k_gather(float* __restrict__ out, int N) {
    __shared__ float ssum[8][128];
    __shared__ float ssq[8][128];
    int lane = threadIdx.x & 31;
    int w    = threadIdx.x >> 5;

    float4 cs = make_float4(0.f, 0.f, 0.f, 0.f);
    float4 cq = make_float4(0.f, 0.f, 0.f, 0.f);

    for (int n0 = (blockIdx.x * 8 + w) * 2; n0 < N; n0 += gridDim.x * 16) {
        int n1 = n0 + 1;
        bool has1 = n1 < N;

        int   s0 = g_start[n0],            c0 = g_cnt[n0];
        int   s1 = has1 ? g_start[n1] : 0, c1 = has1 ? g_cnt[n1] : 0;

        float4 a0 = *(const float4*)(g_h + (size_t)n0 * D + lane * 4);
        float4 a1 = has1 ? *(const float4*)(g_h + (size_t)n1 * D + lane * 4)
                         : make_float4(0.f, 0.f, 0.f, 0.f);

        for (int j = 0; j < c0 || j < c1; j += 32) {
            int m0 = min(32, c0 - j); if (m0 < 0) m0 = 0;
            int m1 = min(32, c1 - j); if (m1 < 0) m1 = 0;
            int idx0 = (lane < m0) ? g_adj[s0 + j + lane] : 0;
            int idx1 = (lane < m1) ? g_adj[s1 + j + lane] : 0;
            int mm = max(m0, m1);

            for (int k = 0; k < mm; k += 4) {
                int e0 = min(m0 - k, 4); // edges this step, node0 (may be <=0)
                int e1 = min(m1 - k, 4);
                float4 v0[4], v1[4];
#pragma unroll
                for (int i = 0; i < 4; i++) {
                    if (i < e0) {
                        int r = __shfl_sync(0xffffffffu, idx0, k + i);
                        v0[i] = *(const float4*)(g_h + (size_t)r * D + lane * 4);
                    }
                }
#pragma unroll
                for (int i = 0; i < 4; i++) {
                    if (i < e1) {
                        int r = __shfl_sync(0xffffffffu, idx1, k + i);
                        v1[i] = *(const float4*)(g_h + (size_t)r * D + lane * 4);
                    }
                }
#pragma unroll
                for (int i = 0; i < 4; i++) {
                    if (i < e0) {
                        a0.x += v0[i].x; a0.y += v0[i].y;
                        a0.z += v0[i].z; a0.w += v0[i].w;
                    }
                }
#pragma unroll
                for (int i = 0; i < 4; i++) {
                    if (i < e1) {
                        a1.x += v1[i].x; a1.y += v1[i].y;
                        a1.z += v1[i].z; a1.w += v1[i].w;
                    }
                }
            }
        }

        float d0 = g_dis[n0];
        float4 o0 = make_float4(a0.x * d0, a0.y * d0, a0.z * d0, a0.w * d0);
        *(float4*)(out + (size_t)n0 * D + lane * 4) = o0;
        cs.x += o0.x; cs.y += o0.y; cs.z += o0.z; cs.w += o0.w;
        cq.x += o0.x * o0.x; cq.y += o0.y * o0.y;
        cq.z += o0.z * o0.z; cq.w += o0.w * o0.w;

        if (has1) {
            float d1 = g_dis[n1];
            float4 o1 = make_float4(a1.x * d1, a1.y * d1, a1.z * d1, a1.w * d1);
            *(float4*)(out + (size_t)n1 * D + lane * 4) = o1;
            cs.x += o1.x; cs.y += o1.y; cs.z += o1.z; cs.w += o1.w;
            cq.x += o1.x * o1.x; cq.y += o1.y * o1.y;
            cq.z += o1.z * o1.z; cq.w += o1.w * o1.w;
        }
    }

    *(float4*)&ssum[w][lane * 4] = cs;
    *(float4*)&ssq[w][lane * 4]  = cq;
    __syncthreads();
    int t = threadIdx.x;
    if (t < D) {
        float a = 0.f, b = 0.f;
#pragma unroll
        for (int w2 = 0; w2 < 8; w2++) { a += ssum[w2][t]; b += ssq[w2][t]; }
        atomicAdd(&g_colstats[t], a);
        atomicAdd(&g_colstats[D + t], b);
    }
}

// ---------------------------------------------------------------------------
// K4: BN (training mode, biased var) + ReLU in place; self-clean cnt/total
// ---------------------------------------------------------------------------
__global__ void k_final(const float* __restrict__ gamma,
                        const float* __restrict__ beta,
                        float* __restrict__ out, int N) {
    __shared__ float sscale[D], sshift[D];
    int t = threadIdx.x;
    if (t < D) {
        float invN = 1.0f / (float)N;
        float mean = g_colstats[t] * invN;
        float var  = g_colstats[D + t] * invN - mean * mean;
        float inv  = rsqrtf(var + 1e-5f);
        float sc   = gamma[t] * inv;
        sscale[t]  = sc;
        sshift[t]  = beta[t] - mean * sc;
    }
    __syncthreads();

    int gid = blockIdx.x * blockDim.x + t;
    if (gid < N) g_cnt[gid] = 0;
    if (gid == 0) g_total = 0;

    size_t total4 = (size_t)N * (D / 4);
    size_t stride = (size_t)gridDim.x * blockDim.x;
    for (size_t i = (size_t)blockIdx.x * blockDim.x + t; i < total4; i += stride) {
        int c = (int)(i & 31) * 4;
        float4 v = ((float4*)out)[i];
        v.x = fmaxf(v.x * sscale[c + 0] + sshift[c + 0], 0.0f);
        v.y = fmaxf(v.y * sscale[c + 1] + sshift[c + 1], 0.0f);
        v.z = fmaxf(v.z * sscale[c + 2] + sshift[c + 2], 0.0f);
        v.w = fmaxf(v.w * sscale[c + 3] + sshift[c + 3], 0.0f);
        ((float4*)out)[i] = v;
    }
}

// ---------------------------------------------------------------------------
extern "C" void kernel_launch(void* const* d_in, const int* in_sizes, int n_in,
                              void* d_out, int out_size) {
    const float* x     = (const float*)d_in[0];
    const int*   pos   = (const int*)d_in[1];   // int32 (JAX canonicalizes int64)
    // d_in[2] = neg_edge_index: weight 0 => no-op, skipped
    const float* W     = (const float*)d_in[3];
    // d_in[4] = b: cancels exactly inside BatchNorm, skipped
    const float* gamma = (const float*)d_in[5];
    const float* beta  = (const float*)d_in[6];
    float*       out   = (float*)d_out;

    const int N  = in_sizes[0] / D;
    const int E  = in_sizes[1] / 2;
    const int GB = (N + 127) / 128;

    k_count <<<256, 256>>>(pos, E);
    k_alloc <<<(N + 255) / 256, 256>>>(N);
    kA      <<<GB + FB, 256>>>(x, W, pos, N, E, GB);
    k_gather<<<592, 256>>>(out, N);
    k_final <<<784, 256>>>(gamma, beta, out, N);
}

// round 6
// speedup vs baseline: 1.2812x; 1.2812x over previous
#include <cuda_runtime.h>
#include <cstdint>

#define D 128
#define N_MAX 50064
#define E_MAX 500000
#define FB 160          // fill blocks appended to kernel A

// ---- device scratch (no allocations; .bss zero at load, kernels self-clean) ----
__device__ float g_h[(size_t)N_MAX * D];   // h' = dis[r] * (x @ W)[r]
__device__ int   g_cnt[N_MAX];             // in-degree (excl. self); zeroed by k_final
__device__ float g_dis[N_MAX];             // rsqrt(1 + cnt)
__device__ int   g_start[N_MAX];
__device__ int   g_cursor[N_MAX];
__device__ int   g_adj[E_MAX];
__device__ int   g_total;                  // ticket; zeroed by k_final
__device__ float g_colstats[2 * D];        // zeroed by k_count

// ---------------------------------------------------------------------------
// K1: in-degree count (grid-stride); block 0 zeros column stats
// ---------------------------------------------------------------------------
__global__ void k_count(const int* __restrict__ pos, int E) {
    if (blockIdx.x == 0) g_colstats[threadIdx.x] = 0.0f;   // 256 == 2*D
    for (int e = blockIdx.x * 256 + threadIdx.x; e < E; e += gridDim.x * 256)
        atomicAdd(&g_cnt[pos[(size_t)E + e]], 1);
}

// ---------------------------------------------------------------------------
// K2: segment allocation — block scan + one atomic ticket; dis; cursor
// ---------------------------------------------------------------------------
__global__ void k_alloc(int N) {
    __shared__ int sh[256];
    __shared__ int base;
    int t = threadIdx.x;
    int i = blockIdx.x * 256 + t;
    int c = (i < N) ? g_cnt[i] : 0;
    sh[t] = c;
    __syncthreads();
    for (int off = 1; off < 256; off <<= 1) {
        int v = (t >= off) ? sh[t - off] : 0;
        __syncthreads();
        sh[t] += v;
        __syncthreads();
    }
    if (t == 255) base = atomicAdd(&g_total, sh[255]);
    __syncthreads();
    if (i < N) {
        int start = base + sh[t] - c;
        g_start[i]  = start;
        g_cursor[i] = start;
        g_dis[i]    = rsqrtf(1.0f + (float)c);
    }
}

// ---------------------------------------------------------------------------
// Kernel A (block-specialized):
//   blocks [0, GB)     : h' = dis[r] * (x @ W)  (fp32x2 GEMM, 128x128 tile)
//   blocks [GB, GB+FB) : CSC adjacency fill (independent of h)
// ---------------------------------------------------------------------------
#define FMA2(acc, a, b) asm("fma.rn.f32x2 %0, %1, %2, %0;" : "+l"(acc) : "l"(a), "l"(b))

__global__ void __launch_bounds__(256) kA(const float* __restrict__ x,
                                          const float* __restrict__ W,
                                          const int* __restrict__ pos,
                                          int N, int E, int GB) {
    if (blockIdx.x >= GB) {
        // ---- fill path ----
        int b = blockIdx.x - GB;
        for (int e = b * 256 + threadIdx.x; e < E; e += FB * 256) {
            int col = pos[(size_t)E + e];
            int p = atomicAdd(&g_cursor[col], 1);
            g_adj[p] = pos[e];
        }
        return;
    }

    // ---- GEMM path ----
    __shared__ float xs[16][128];   // transposed x tile
    __shared__ float ws[16][128];   // W tile

    const int t  = threadIdx.x;
    const int r0 = blockIdx.x * 128;
    const int cg = t & 15;
    const int rg = t >> 4;

    unsigned long long acc[8][4];
#pragma unroll
    for (int i = 0; i < 8; i++)
#pragma unroll
        for (int j = 0; j < 4; j++) acc[i][j] = 0ull;

    for (int k0 = 0; k0 < D; k0 += 16) {
        __syncthreads();
#pragma unroll
        for (int u = 0; u < 2; u++) {
            int id  = t + u * 256;
            int row = id >> 2;
            int kq  = (id & 3) * 4;
            float4 v = make_float4(0.f, 0.f, 0.f, 0.f);
            int gr = r0 + row;
            if (gr < N) v = *(const float4*)(x + (size_t)gr * D + k0 + kq);
            xs[kq + 0][row] = v.x;
            xs[kq + 1][row] = v.y;
            xs[kq + 2][row] = v.z;
            xs[kq + 3][row] = v.w;
        }
#pragma unroll
        for (int u = 0; u < 2; u++) {
            int id = t + u * 256;
            int kk = id >> 5;
            int c4 = id & 31;
            *(float4*)&ws[kk][c4 * 4] =
                *(const float4*)(W + (size_t)(k0 + kk) * D + c4 * 4);
        }
        __syncthreads();

#pragma unroll
        for (int kk = 0; kk < 16; kk++) {
            ulonglong2 wA = *(const ulonglong2*)&ws[kk][cg * 8];
            ulonglong2 wB = *(const ulonglong2*)&ws[kk][cg * 8 + 4];
            float4 xa = *(const float4*)&xs[kk][rg * 8];
            float4 xb = *(const float4*)&xs[kk][rg * 8 + 4];
            float xv[8] = {xa.x, xa.y, xa.z, xa.w, xb.x, xb.y, xb.z, xb.w};
#pragma unroll
            for (int i = 0; i < 8; i++) {
                unsigned long long xd;
                asm("mov.b64 %0, {%1, %1};" : "=l"(xd) : "f"(xv[i]));
                FMA2(acc[i][0], xd, wA.x);
                FMA2(acc[i][1], xd, wA.y);
                FMA2(acc[i][2], xd, wB.x);
                FMA2(acc[i][3], xd, wB.y);
            }
        }
    }

#pragma unroll
    for (int i = 0; i < 8; i++) {
        int gr = r0 + rg * 8 + i;
        if (gr < N) {
            float s = g_dis[gr];
            float2 p0 = *(float2*)&acc[i][0];
            float2 p1 = *(float2*)&acc[i][1];
            float2 p2 = *(float2*)&acc[i][2];
            float2 p3 = *(float2*)&acc[i][3];
            *(float4*)(g_h + (size_t)gr * D + cg * 8) =
                make_float4(p0.x * s, p0.y * s, p1.x * s, p1.y * s);
            *(float4*)(g_h + (size_t)gr * D + cg * 8 + 4) =
                make_float4(p2.x * s, p2.y * s, p3.x * s, p3.y * s);
        }
    }
}

// ---------------------------------------------------------------------------
// K3: gather — one node per warp, pure v4 adds (h pre-scaled by dis),
//     fused column stats.  out[c] = dis[c] * (h'[c] + sum_in h'[r])
// ---------------------------------------------------------------------------
__global__ void __launch_bounds__(256) k_gather(float* __restrict__ out, int N) {
    __shared__ float ssum[8][128];
    __shared__ float ssq[8][128];
    int lane = threadIdx.x & 31;
    int w    = threadIdx.x >> 5;

    float4 cs = make_float4(0.f, 0.f, 0.f, 0.f);
    float4 cq = make_float4(0.f, 0.f, 0.f, 0.f);

    for (int node = blockIdx.x * 8 + w; node < N; node += gridDim.x * 8) {
        int start = g_start[node];
        int cnt   = g_cnt[node];

        float4 acc = *(const float4*)(g_h + (size_t)node * D + lane * 4);  // self

        for (int j = 0; j < cnt; j += 32) {
            int m = min(32, cnt - j);
            int idx = (lane < m) ? g_adj[start + j + lane] : 0;
            int k = 0;
            for (; k + 4 <= m; k += 4) {     // 4-deep MLP, pure adds
                int rA = __shfl_sync(0xffffffffu, idx, k + 0);
                int rB = __shfl_sync(0xffffffffu, idx, k + 1);
                int rC = __shfl_sync(0xffffffffu, idx, k + 2);
                int rD = __shfl_sync(0xffffffffu, idx, k + 3);
                float4 vA = *(const float4*)(g_h + (size_t)rA * D + lane * 4);
                float4 vB = *(const float4*)(g_h + (size_t)rB * D + lane * 4);
                float4 vC = *(const float4*)(g_h + (size_t)rC * D + lane * 4);
                float4 vD = *(const float4*)(g_h + (size_t)rD * D + lane * 4);
                acc.x += vA.x + vB.x + vC.x + vD.x;
                acc.y += vA.y + vB.y + vC.y + vD.y;
                acc.z += vA.z + vB.z + vC.z + vD.z;
                acc.w += vA.w + vB.w + vC.w + vD.w;
            }
            for (; k < m; k++) {
                int r = __shfl_sync(0xffffffffu, idx, k);
                float4 v = *(const float4*)(g_h + (size_t)r * D + lane * 4);
                acc.x += v.x; acc.y += v.y; acc.z += v.z; acc.w += v.w;
            }
        }

        float s = g_dis[node];
        float4 o = make_float4(acc.x * s, acc.y * s, acc.z * s, acc.w * s);
        *(float4*)(out + (size_t)node * D + lane * 4) = o;
        cs.x += o.x; cs.y += o.y; cs.z += o.z; cs.w += o.w;
        cq.x += o.x * o.x; cq.y += o.y * o.y;
        cq.z += o.z * o.z; cq.w += o.w * o.w;
    }

    *(float4*)&ssum[w][lane * 4] = cs;
    *(float4*)&ssq[w][lane * 4]  = cq;
    __syncthreads();
    int t = threadIdx.x;
    if (t < D) {
        float a = 0.f, b = 0.f;
#pragma unroll
        for (int w2 = 0; w2 < 8; w2++) { a += ssum[w2][t]; b += ssq[w2][t]; }
        atomicAdd(&g_colstats[t], a);
        atomicAdd(&g_colstats[D + t], b);
    }
}

// ---------------------------------------------------------------------------
// K4: BN (training mode, biased var) + ReLU in place; self-clean cnt/total
// ---------------------------------------------------------------------------
__global__ void k_final(const float* __restrict__ gamma,
                        const float* __restrict__ beta,
                        float* __restrict__ out, int N) {
    __shared__ float sscale[D], sshift[D];
    int t = threadIdx.x;
    if (t < D) {
        float invN = 1.0f / (float)N;
        float mean = g_colstats[t] * invN;
        float var  = g_colstats[D + t] * invN - mean * mean;
        float inv  = rsqrtf(var + 1e-5f);
        float sc   = gamma[t] * inv;
        sscale[t]  = sc;
        sshift[t]  = beta[t] - mean * sc;
    }
    __syncthreads();

    int gid = blockIdx.x * blockDim.x + t;
    if (gid < N) g_cnt[gid] = 0;
    if (gid == 0) g_total = 0;

    size_t total4 = (size_t)N * (D / 4);
    size_t stride = (size_t)gridDim.x * blockDim.x;
    for (size_t i = (size_t)blockIdx.x * blockDim.x + t; i < total4; i += stride) {
        int c = (int)(i & 31) * 4;
        float4 v = ((float4*)out)[i];
        v.x = fmaxf(v.x * sscale[c + 0] + sshift[c + 0], 0.0f);
        v.y = fmaxf(v.y * sscale[c + 1] + sshift[c + 1], 0.0f);
        v.z = fmaxf(v.z * sscale[c + 2] + sshift[c + 2], 0.0f);
        v.w = fmaxf(v.w * sscale[c + 3] + sshift[c + 3], 0.0f);
        ((float4*)out)[i] = v;
    }
}

// ---------------------------------------------------------------------------
extern "C" void kernel_launch(void* const* d_in, const int* in_sizes, int n_in,
                              void* d_out, int out_size) {
    const float* x     = (const float*)d_in[0];
    const int*   pos   = (const int*)d_in[1];   // int32 (JAX canonicalizes int64)
    // d_in[2] = neg_edge_index: weight 0 => no-op, skipped
    const float* W     = (const float*)d_in[3];
    // d_in[4] = b: cancels exactly inside BatchNorm, skipped
    const float* gamma = (const float*)d_in[5];
    const float* beta  = (const float*)d_in[6];
    float*       out   = (float*)d_out;

    const int N  = in_sizes[0] / D;
    const int E  = in_sizes[1] / 2;
    const int GB = (N + 127) / 128;

    k_count <<<256, 256>>>(pos, E);
    k_alloc <<<(N + 255) / 256, 256>>>(N);
    kA      <<<GB + FB, 256>>>(x, W, pos, N, E, GB);
    k_gather<<<888, 256>>>(out, N);     // 148 SMs x 6 blocks (42 regs -> 6/SM)
    k_final <<<784, 256>>>(gamma, beta, out, N);
}

// round 8
// speedup vs baseline: 1.2941x; 1.0101x over previous
#include <cuda_runtime.h>
#include <cstdint>

#define D 128
#define N_MAX 50064
#define E_MAX 660000    // padded CSC: E + 3*N worst case
#define FB 160          // fill blocks appended to kernel A

// ---- device scratch (no allocations; .bss zero at load, kernels self-clean) ----
__device__ float g_h[(size_t)N_MAX * D];   // h' = dis[r]*(x@W)[r]; row N stays ZERO (dummy)
__device__ int   g_cnt[N_MAX];             // in-degree (excl. self); zeroed by k_final
__device__ float g_dis[N_MAX];             // rsqrt(1 + cnt)
__device__ int   g_start[N_MAX];
__device__ int   g_cursor[N_MAX];
__device__ int   g_adj[E_MAX];
__device__ int   g_total;                  // ticket; zeroed by k_final
__device__ float g_colstats[2 * D];        // zeroed by k_count

__device__ __forceinline__ unsigned long long add2(unsigned long long a,
                                                   unsigned long long b) {
    unsigned long long r;
    asm("add.rn.f32x2 %0, %1, %2;" : "=l"(r) : "l"(a), "l"(b));
    return r;
}

// ---------------------------------------------------------------------------
// K1: in-degree count (grid-stride); block 0 zeros column stats
// ---------------------------------------------------------------------------
__global__ void k_count(const int* __restrict__ pos, int E) {
    if (blockIdx.x == 0) g_colstats[threadIdx.x] = 0.0f;   // 256 == 2*D
    for (int e = blockIdx.x * 256 + threadIdx.x; e < E; e += gridDim.x * 256)
        atomicAdd(&g_cnt[pos[(size_t)E + e]], 1);
}

// ---------------------------------------------------------------------------
// K2: segment allocation with 4-padding — block scan + one atomic ticket.
//     Pad slots get dummy index N (zero row of g_h) so gather has NO tail.
// ---------------------------------------------------------------------------
__global__ void k_alloc(int N) {
    __shared__ int sh[256];
    __shared__ int base;
    int t = threadIdx.x;
    int i = blockIdx.x * 256 + t;
    int c    = (i < N) ? g_cnt[i] : 0;
    int cpad = (c + 3) & ~3;
    sh[t] = cpad;
    __syncthreads();
    for (int off = 1; off < 256; off <<= 1) {
        int v = (t >= off) ? sh[t - off] : 0;
        __syncthreads();
        sh[t] += v;
        __syncthreads();
    }
    if (t == 255) base = atomicAdd(&g_total, sh[255]);
    __syncthreads();
    if (i < N) {
        int start = base + sh[t] - cpad;
        g_start[i]  = start;
        g_cursor[i] = start;
        g_dis[i]    = rsqrtf(1.0f + (float)c);
#pragma unroll
        for (int p = 0; p < 3; p++)                 // <=3 dummy slots
            if (c + p < cpad) g_adj[start + c + p] = N;
    }
}

// ---------------------------------------------------------------------------
// Kernel A (block-specialized):
//   blocks [0, GB)     : h' = dis[r] * (x @ W)  (fp32x2 GEMM, 128x128 tile)
//   blocks [GB, GB+FB) : CSC adjacency fill (independent of h)
// ---------------------------------------------------------------------------
#define FMA2(acc, a, b) asm("fma.rn.f32x2 %0, %1, %2, %0;" : "+l"(acc) : "l"(a), "l"(b))

__global__ void __launch_bounds__(256) kA(const float* __restrict__ x,
                                          const float* __restrict__ W,
                                          const int* __restrict__ pos,
                                          int N, int E, int GB) {
    if (blockIdx.x >= GB) {
        // ---- fill path ----
        int b = blockIdx.x - GB;
        for (int e = b * 256 + threadIdx.x; e < E; e += FB * 256) {
            int col = pos[(size_t)E + e];
            int p = atomicAdd(&g_cursor[col], 1);
            g_adj[p] = pos[e];
        }
        return;
    }

    // ---- GEMM path ----
    __shared__ float xs[16][128];   // transposed x tile
    __shared__ float ws[16][128];   // W tile

    const int t  = threadIdx.x;
    const int r0 = blockIdx.x * 128;
    const int cg = t & 15;
    const int rg = t >> 4;

    unsigned long long acc[8][4];
#pragma unroll
    for (int i = 0; i < 8; i++)
#pragma unroll
        for (int j = 0; j < 4; j++) acc[i][j] = 0ull;

    for (int k0 = 0; k0 < D; k0 += 16) {
        __syncthreads();
#pragma unroll
        for (int u = 0; u < 2; u++) {
            int id  = t + u * 256;
            int row = id >> 2;
            int kq  = (id & 3) * 4;
            float4 v = make_float4(0.f, 0.f, 0.f, 0.f);
            int gr = r0 + row;
            if (gr < N) v = *(const float4*)(x + (size_t)gr * D + k0 + kq);
            xs[kq + 0][row] = v.x;
            xs[kq + 1][row] = v.y;
            xs[kq + 2][row] = v.z;
            xs[kq + 3][row] = v.w;
        }
#pragma unroll
        for (int u = 0; u < 2; u++) {
            int id = t + u * 256;
            int kk = id >> 5;
            int c4 = id & 31;
            *(float4*)&ws[kk][c4 * 4] =
                *(const float4*)(W + (size_t)(k0 + kk) * D + c4 * 4);
        }
        __syncthreads();

#pragma unroll
        for (int kk = 0; kk < 16; kk++) {
            ulonglong2 wA = *(const ulonglong2*)&ws[kk][cg * 8];
            ulonglong2 wB = *(const ulonglong2*)&ws[kk][cg * 8 + 4];
            float4 xa = *(const float4*)&xs[kk][rg * 8];
            float4 xb = *(const float4*)&xs[kk][rg * 8 + 4];
            float xv[8] = {xa.x, xa.y, xa.z, xa.w, xb.x, xb.y, xb.z, xb.w};
#pragma unroll
            for (int i = 0; i < 8; i++) {
                unsigned long long xd;
                asm("mov.b64 %0, {%1, %1};" : "=l"(xd) : "f"(xv[i]));
                FMA2(acc[i][0], xd, wA.x);
                FMA2(acc[i][1], xd, wA.y);
                FMA2(acc[i][2], xd, wB.x);
                FMA2(acc[i][3], xd, wB.y);
            }
        }
    }

#pragma unroll
    for (int i = 0; i < 8; i++) {
        int gr = r0 + rg * 8 + i;
        if (gr < N) {
            float s = g_dis[gr];
            float2 p0 = *(float2*)&acc[i][0];
            float2 p1 = *(float2*)&acc[i][1];
            float2 p2 = *(float2*)&acc[i][2];
            float2 p3 = *(float2*)&acc[i][3];
            *(float4*)(g_h + (size_t)gr * D + cg * 8) =
                make_float4(p0.x * s, p0.y * s, p1.x * s, p1.y * s);
            *(float4*)(g_h + (size_t)gr * D + cg * 8 + 4) =
                make_float4(p2.x * s, p2.y * s, p3.x * s, p3.y * s);
        }
    }
}

// ---------------------------------------------------------------------------
// K3: gather — one node per warp, padded segments (NO serial tail),
//     packed f32x2 accumulation, fused column stats.
//     out[c] = dis[c] * (h'[c] + sum_in h'[r])
// ---------------------------------------------------------------------------
__global__ void __launch_bounds__(256) k_gather(float* __restrict__ out, int N) {
    __shared__ float ssum[8][128];
    __shared__ float ssq[8][128];
    int lane = threadIdx.x & 31;
    int w    = threadIdx.x >> 5;

    float4 cs = make_float4(0.f, 0.f, 0.f, 0.f);
    float4 cq = make_float4(0.f, 0.f, 0.f, 0.f);

    for (int node = blockIdx.x * 8 + w; node < N; node += gridDim.x * 8) {
        int start = g_start[node];
        int cntp  = (g_cnt[node] + 3) & ~3;   // padded; pad slots -> zero row

        ulonglong2 acc = *(const ulonglong2*)(g_h + (size_t)node * D + lane * 4);

        for (int j = 0; j < cntp; j += 32) {
            int m = min(32, cntp - j);        // multiple of 4
            int idx = (lane < m) ? g_adj[start + j + lane] : 0;
#pragma unroll 2
            for (int k = 0; k < m; k += 4) {  // 4-deep MLP, packed adds
                int rA = __shfl_sync(0xffffffffu, idx, k + 0);
                int rB = __shfl_sync(0xffffffffu, idx, k + 1);
                int rC = __shfl_sync(0xffffffffu, idx, k + 2);
                int rD = __shfl_sync(0xffffffffu, idx, k + 3);
                ulonglong2 pA = *(const ulonglong2*)(g_h + (size_t)rA * D + lane * 4);
                ulonglong2 pB = *(const ulonglong2*)(g_h + (size_t)rB * D + lane * 4);
                ulonglong2 pC = *(const ulonglong2*)(g_h + (size_t)rC * D + lane * 4);
                ulonglong2 pD = *(const ulonglong2*)(g_h + (size_t)rD * D + lane * 4);
                acc.x = add2(acc.x, add2(add2(pA.x, pB.x), add2(pC.x, pD.x)));
                acc.y = add2(acc.y, add2(add2(pA.y, pB.y), add2(pC.y, pD.y)));
            }
        }

        float s = g_dis[node];
        float2 xy = *(float2*)&acc.x;
        float2 zw = *(float2*)&acc.y;
        float4 o = make_float4(xy.x * s, xy.y * s, zw.x * s, zw.y * s);
        *(float4*)(out + (size_t)node * D + lane * 4) = o;
        cs.x += o.x; cs.y += o.y; cs.z += o.z; cs.w += o.w;
        cq.x += o.x * o.x; cq.y += o.y * o.y;
        cq.z += o.z * o.z; cq.w += o.w * o.w;
    }

    *(float4*)&ssum[w][lane * 4] = cs;
    *(float4*)&ssq[w][lane * 4]  = cq;
    __syncthreads();
    int t = threadIdx.x;
    if (t < D) {
        float a = 0.f, b = 0.f;
#pragma unroll
        for (int w2 = 0; w2 < 8; w2++) { a += ssum[w2][t]; b += ssq[w2][t]; }
        atomicAdd(&g_colstats[t], a);
        atomicAdd(&g_colstats[D + t], b);
    }
}

// ---------------------------------------------------------------------------
// K4: BN (training mode, biased var) + ReLU in place; self-clean cnt/total
// ---------------------------------------------------------------------------
__global__ void k_final(const float* __restrict__ gamma,
                        const float* __restrict__ beta,
                        float* __restrict__ out, int N) {
    __shared__ float sscale[D], sshift[D];
    int t = threadIdx.x;
    if (t < D) {
        float invN = 1.0f / (float)N;
        float mean = g_colstats[t] * invN;
        float var  = g_colstats[D + t] * invN - mean * mean;
        float inv  = rsqrtf(var + 1e-5f);
        float sc   = gamma[t] * inv;
        sscale[t]  = sc;
        sshift[t]  = beta[t] - mean * sc;
    }
    __syncthreads();

    int gid = blockIdx.x * blockDim.x + t;
    if (gid < N) g_cnt[gid] = 0;
    if (gid == 0) g_total = 0;

    size_t total4 = (size_t)N * (D / 4);
    size_t stride = (size_t)gridDim.x * blockDim.x;
    for (size_t i = (size_t)blockIdx.x * blockDim.x + t; i < total4; i += stride) {
        int c = (int)(i & 31) * 4;
        float4 v = ((float4*)out)[i];
        v.x = fmaxf(v.x * sscale[c + 0] + sshift[c + 0], 0.0f);
        v.y = fmaxf(v.y * sscale[c + 1] + sshift[c + 1], 0.0f);
        v.z = fmaxf(v.z * sscale[c + 2] + sshift[c + 2], 0.0f);
        v.w = fmaxf(v.w * sscale[c + 3] + sshift[c + 3], 0.0f);
        ((float4*)out)[i] = v;
    }
}

// ---------------------------------------------------------------------------
extern "C" void kernel_launch(void* const* d_in, const int* in_sizes, int n_in,
                              void* d_out, int out_size) {
    const float* x     = (const float*)d_in[0];
    const int*   pos   = (const int*)d_in[1];   // int32 (JAX canonicalizes int64)
    // d_in[2] = neg_edge_index: weight 0 => no-op, skipped
    const float* W     = (const float*)d_in[3];
    // d_in[4] = b: cancels exactly inside BatchNorm, skipped
    const float* gamma = (const float*)d_in[5];
    const float* beta  = (const float*)d_in[6];
    float*       out   = (float*)d_out;

    const int N  = in_sizes[0] / D;
    const int E  = in_sizes[1] / 2;
    const int GB = (N + 127) / 128;

    k_count <<<256, 256>>>(pos, E);
    k_alloc <<<(N + 255) / 256, 256>>>(N);
    kA      <<<GB + FB, 256>>>(x, W, pos, N, E, GB);
    k_gather<<<888, 256>>>(out, N);     // 148 SMs x 6 blocks
    k_final <<<784, 256>>>(gamma, beta, out, N);
}